// round 9
// baseline (speedup 1.0000x reference)
#include <cuda_runtime.h>
#include <cuda_bf16.h>
#include <cstdint>

// ---------------- problem constants ----------------
#define kH     8
#define kD     512
#define kDK    64
#define kBG    24          // B*G = 4*6
#define kSEQ   1024
#define kROWS  (kBG * kSEQ)    // 24576
#define kBGH   (kBG * kH)      // 192
#define kYELEMS (kBG * kD)     // 12288
#define kSCALE (1.0f / 1200.0f)   // 1/(sqrt(64)*150)
#define kPELEMS 201326592LL
#define kITEMS (kBGH * 8)      // 1536 items = (bgh, 128-row octant)
#define kCTAS  148

typedef unsigned long long u64;
typedef unsigned int u32;

// ---------------- scratch ----------------
__device__ __align__(16) __nv_bfloat16 g_qx[kROWS * kD];   // bf16 query input
__device__ __align__(16) __nv_bfloat16 g_kx[kROWS * kD];   // bf16 key input
__device__ __align__(16) __nv_bfloat16 g_wq[kD * kD];      // bf16 Wq
__device__ __align__(16) __nv_bfloat16 g_wk[kD * kD];      // bf16 Wk
__device__ __align__(16) __nv_bfloat16 g_qb[kROWS * kD];   // bf16 Q projection
__device__ __align__(16) __nv_bfloat16 g_kb[kROWS * kD];   // bf16 K projection
__device__ float g_pbar[kBGH * kSEQ];
__device__ float g_w[kBG * kH * kD];

// ---------------- helpers ----------------
__device__ __forceinline__ u32 pack_bf2(float x, float y) {
    __nv_bfloat162 h = __floats2bfloat162_rn(x, y);
    return *reinterpret_cast<u32*>(&h);
}
__device__ __forceinline__ void mma_bf16(float c[4], const u32 a[4],
                                         u32 b0, u32 b1) {
    asm volatile(
        "mma.sync.aligned.m16n8k16.row.col.f32.bf16.bf16.f32 "
        "{%0,%1,%2,%3}, {%4,%5,%6,%7}, {%8,%9}, {%0,%1,%2,%3};\n"
        : "+f"(c[0]), "+f"(c[1]), "+f"(c[2]), "+f"(c[3])
        : "r"(a[0]), "r"(a[1]), "r"(a[2]), "r"(a[3]), "r"(b0), "r"(b1));
}
// packed f32x2
__device__ __forceinline__ u64 pk2(float x, float y) {
    u64 r; asm("mov.b64 %0, {%1,%2};" : "=l"(r) : "f"(x), "f"(y)); return r;
}
__device__ __forceinline__ void upk2(float& x, float& y, u64 v) {
    asm("mov.b64 {%0,%1}, %2;" : "=f"(x), "=f"(y) : "l"(v));
}
__device__ __forceinline__ u64 fma2(u64 a, u64 b, u64 c) {
    u64 d; asm("fma.rn.f32x2 %0,%1,%2,%3;" : "=l"(d) : "l"(a), "l"(b), "l"(c)); return d;
}
__device__ __forceinline__ u64 mul2(u64 a, u64 b) {
    u64 d; asm("mul.rn.f32x2 %0,%1,%2;" : "=l"(d) : "l"(a), "l"(b)); return d;
}
__device__ __forceinline__ u64 add2(u64 a, u64 b) {
    u64 d; asm("add.rn.f32x2 %0,%1,%2;" : "=l"(d) : "l"(a), "l"(b)); return d;
}

// ---------------- K0: zero accumulators ----------------
#define kZTOT (kBGH * kSEQ + kBG * kH * kD)
__global__ void zero_kernel() {
    int i = blockIdx.x * blockDim.x + threadIdx.x;
    if (i < kBGH * kSEQ) g_pbar[i] = 0.0f;
    else if (i < kZTOT) g_w[i - kBGH * kSEQ] = 0.0f;
}

// ---------------- K0b: one-shot fp32 -> bf16 conversion ----------------
#define kCVT_Q  3145728
#define kCVT_K  (kCVT_Q * 2)          // 6291456
#define kCVT_WQ (kCVT_K + 65536)      // 6356992
#define kCVT_WK (kCVT_WQ + 65536)     // 6422528
__global__ __launch_bounds__(256) void cvt_kernel(
    const float* __restrict__ query, const float* __restrict__ key,
    const float* __restrict__ Wq, const float* __restrict__ Wk)
{
    long long i = (long long)blockIdx.x * blockDim.x + threadIdx.x;
    if (i >= kCVT_WK) return;
    const float* src;
    __nv_bfloat16* dst;
    long long off;
    if (i < kCVT_Q)       { src = query; dst = g_qx; off = i; }
    else if (i < kCVT_K)  { src = key;   dst = g_kx; off = i - kCVT_Q; }
    else if (i < kCVT_WQ) { src = Wq;    dst = g_wq; off = i - kCVT_K; }
    else                  { src = Wk;    dst = g_wk; off = i - kCVT_WQ; }
    float4 v = *(const float4*)(src + off * 4);
    *(uint2*)(dst + off * 4) = make_uint2(pack_bf2(v.x, v.y), pack_bf2(v.z, v.w));
}

// ---------------- K1: Q & K projections (bf16 inputs) ----------
__global__ __launch_bounds__(256, 2) void proj_kernel(
    const float* __restrict__ bq, const float* __restrict__ bk)
{
    __shared__ __nv_bfloat16 As[128 * 72];
    __shared__ __nv_bfloat16 Bs[128 * 72];

    const int z = blockIdx.z;
    const __nv_bfloat16* X = z ? g_kx : g_qx;
    const __nv_bfloat16* W = z ? g_wk : g_wq;
    const float* bias = z ? bk : bq;
    __nv_bfloat16* out = z ? g_kb : g_qb;

    const int mbase = blockIdx.x * 128;
    const int nbase = blockIdx.y * 128;
    const int tid = threadIdx.x;
    const int lane = tid & 31, wid = tid >> 5;
    const int wm = wid >> 1, wn = wid & 1;
    const int g = lane >> 2, t4 = lane & 3;

    float acc[2][8][4];
#pragma unroll
    for (int i = 0; i < 2; i++)
#pragma unroll
        for (int t = 0; t < 8; t++)
#pragma unroll
            for (int c = 0; c < 4; c++) acc[i][t][c] = 0.0f;

    for (int kc = 0; kc < 512; kc += 64) {
#pragma unroll
        for (int it = 0; it < 4; it++) {
            int idx = tid + it * 256;
            int r = idx >> 3, c16 = idx & 7;
            *(uint4*)(As + r * 72 + c16 * 8) =
                *(const uint4*)(X + (size_t)(mbase + r) * 512 + kc + c16 * 8);
            *(uint4*)(Bs + r * 72 + c16 * 8) =
                *(const uint4*)(W + (size_t)(nbase + r) * 512 + kc + c16 * 8);
        }
        __syncthreads();

#pragma unroll
        for (int kk = 0; kk < 4; kk++) {
            u32 a[2][4];
#pragma unroll
            for (int i = 0; i < 2; i++) {
                int rb = wm * 32 + i * 16;
                a[i][0] = *(const u32*)(As + (rb + g) * 72 + kk * 16 + t4 * 2);
                a[i][1] = *(const u32*)(As + (rb + 8 + g) * 72 + kk * 16 + t4 * 2);
                a[i][2] = *(const u32*)(As + (rb + g) * 72 + kk * 16 + 8 + t4 * 2);
                a[i][3] = *(const u32*)(As + (rb + 8 + g) * 72 + kk * 16 + 8 + t4 * 2);
            }
#pragma unroll
            for (int t = 0; t < 8; t++) {
                int srow = wn * 64 + t * 8 + g;
                u32 b0 = *(const u32*)(Bs + srow * 72 + kk * 16 + t4 * 2);
                u32 b1 = *(const u32*)(Bs + srow * 72 + kk * 16 + 8 + t4 * 2);
                mma_bf16(acc[0][t], a[0], b0, b1);
                mma_bf16(acc[1][t], a[1], b0, b1);
            }
        }
        __syncthreads();
    }

#pragma unroll
    for (int i = 0; i < 2; i++) {
#pragma unroll
        for (int t = 0; t < 8; t++) {
            int row0 = mbase + wm * 32 + i * 16 + g;
            int col  = nbase + wn * 64 + t * 8 + t4 * 2;
            float b0v = bias[col], b1v = bias[col + 1];
            *(u32*)(out + (size_t)row0 * 512 + col) =
                pack_bf2(acc[i][t][0] + b0v, acc[i][t][1] + b1v);
            *(u32*)(out + (size_t)(row0 + 8) * 512 + col) =
                pack_bf2(acc[i][t][2] + b0v, acc[i][t][3] + b1v);
        }
    }
}

// ---------------- K2: persistent fused attention, K strip in registers ----------
// 148 CTAs x 512 threads. Each warp owns 64 K-columns: its B fragments for one
// bgh are 64 u32 registers, loaded directly from gmem (same addresses the old
// smem path produced). No K smem at all.
#define ATTN_SMEM (2*32*72*2 + 16*32*4 + 32*4)

__global__ __launch_bounds__(512, 1) void attn_kernel(float* __restrict__ p_out)
{
    extern __shared__ char smem[];
    __nv_bfloat16* Qs = (__nv_bfloat16*)smem;                 // 2 x (32 x 72)
    float* rowpart = (float*)(Qs + 2 * 32 * 72);              // 16 x 32
    float* rinv = rowpart + 16 * 32;                          // 32

    const int cta = blockIdx.x;
    const int it0 = (cta * kITEMS) / kCTAS;
    const int it1 = ((cta + 1) * kITEMS) / kCTAS;
    const int tid = threadIdx.x;
    const int lane = tid & 31, w = tid >> 5;
    const int g = lane >> 2, t4 = lane & 3;

    const u64 SC2  = pk2(kSCALE, kSCALE);
    const u64 C24  = pk2(1.0f/24.0f, 1.0f/24.0f);
    const u64 C6   = pk2(1.0f/6.0f, 1.0f/6.0f);
    const u64 CH   = pk2(0.5f, 0.5f);
    const u64 ONE2 = pk2(1.0f, 1.0f);

    const bool wr = (p_out != nullptr);
    int cur_bgh = -1;

    u32 breg[4][8][2];   // K fragments for this warp's 64 columns (one bgh)

    for (int item = it0; item < it1; item++) {
        const int bgh = item >> 3, oct = item & 7;
        const int bg = bgh >> 3, h = bgh & 7;

        // load K fragments once per bgh (register-resident)
        if (bgh != cur_bgh) {
            cur_bgh = bgh;
            const __nv_bfloat16* kb =
                g_kb + ((size_t)(bg * kSEQ + w * 64 + g)) * 512 + h * 64 + t4 * 2;
#pragma unroll
            for (int t = 0; t < 8; t++) {
                const __nv_bfloat16* row = kb + (size_t)t * 8 * 512;
#pragma unroll
                for (int kk = 0; kk < 4; kk++) {
                    breg[kk][t][0] = *(const u32*)(row + kk * 16);
                    breg[kk][t][1] = *(const u32*)(row + kk * 16 + 8);
                }
            }
        }
        // load first Q tile (32 x 64) into buffer 0
        if (tid < 256) {
            int r = tid >> 3, c8 = tid & 7;
            uint4 v = *(const uint4*)(g_qb + ((size_t)(bg * kSEQ + oct * 128 + r)) * 512 + h * 64 + c8 * 8);
            uint2* dst = (uint2*)(Qs + r * 72 + c8 * 8);
            dst[0] = make_uint2(v.x, v.y); dst[1] = make_uint2(v.z, v.w);
        }
        __syncthreads();

        u64 cs2[8];
#pragma unroll
        for (int t = 0; t < 8; t++) cs2[t] = 0ULL;

        for (int qt = 0; qt < 4; qt++) {
            const __nv_bfloat16* Qc = Qs + (qt & 1) * (32 * 72);

            float acc[2][8][4];
#pragma unroll
            for (int i = 0; i < 2; i++)
#pragma unroll
                for (int t = 0; t < 8; t++)
#pragma unroll
                    for (int c = 0; c < 4; c++) acc[i][t][c] = 0.0f;

#pragma unroll
            for (int kk = 0; kk < 4; kk++) {
                u32 a[2][4];
#pragma unroll
                for (int i = 0; i < 2; i++) {
                    int rb = i * 16;
                    a[i][0] = *(const u32*)(Qc + (rb + g) * 72 + kk * 16 + t4 * 2);
                    a[i][1] = *(const u32*)(Qc + (rb + 8 + g) * 72 + kk * 16 + t4 * 2);
                    a[i][2] = *(const u32*)(Qc + (rb + g) * 72 + kk * 16 + 8 + t4 * 2);
                    a[i][3] = *(const u32*)(Qc + (rb + 8 + g) * 72 + kk * 16 + 8 + t4 * 2);
                }
#pragma unroll
                for (int t = 0; t < 8; t++) {
                    mma_bf16(acc[0][t], a[0], breg[kk][t][0], breg[kk][t][1]);
                    mma_bf16(acc[1][t], a[1], breg[kk][t][0], breg[kk][t][1]);
                }
            }

            // prefetch next Q tile into the other buffer
            if (qt < 3 && tid < 256) {
                int r = tid >> 3, c8 = tid & 7;
                uint4 v = *(const uint4*)(g_qb +
                    ((size_t)(bg * kSEQ + oct * 128 + (qt + 1) * 32 + r)) * 512 + h * 64 + c8 * 8);
                uint2* dst = (uint2*)(Qs + ((qt & 1) ^ 1) * (32 * 72) + r * 72 + c8 * 8);
                dst[0] = make_uint2(v.x, v.y); dst[1] = make_uint2(v.z, v.w);
            }

            // exp (packed f32x2, degree-4 poly) written back into acc; row partials
            u64 rs2[2][2] = {0ULL, 0ULL, 0ULL, 0ULL};
#pragma unroll
            for (int i = 0; i < 2; i++) {
#pragma unroll
                for (int t = 0; t < 8; t++) {
                    u64 x01 = mul2(pk2(acc[i][t][0], acc[i][t][1]), SC2);
                    u64 p01 = fma2(x01, C24, C6);
                    p01 = fma2(p01, x01, CH);
                    p01 = fma2(p01, x01, ONE2);
                    p01 = fma2(p01, x01, ONE2);
                    upk2(acc[i][t][0], acc[i][t][1], p01);
                    rs2[i][0] = add2(rs2[i][0], p01);

                    u64 x23 = mul2(pk2(acc[i][t][2], acc[i][t][3]), SC2);
                    u64 p23 = fma2(x23, C24, C6);
                    p23 = fma2(p23, x23, CH);
                    p23 = fma2(p23, x23, ONE2);
                    p23 = fma2(p23, x23, ONE2);
                    upk2(acc[i][t][2], acc[i][t][3], p23);
                    rs2[i][1] = add2(rs2[i][1], p23);
                }
            }
            float r4[4];
#pragma unroll
            for (int i = 0; i < 2; i++) {
                float lo, hi;
                upk2(lo, hi, rs2[i][0]); r4[i * 2]     = lo + hi;
                upk2(lo, hi, rs2[i][1]); r4[i * 2 + 1] = lo + hi;
            }
#pragma unroll
            for (int j = 0; j < 4; j++) {
                r4[j] += __shfl_xor_sync(0xffffffffu, r4[j], 1);
                r4[j] += __shfl_xor_sync(0xffffffffu, r4[j], 2);
            }
            if (t4 == 0) {
                rowpart[w * 32 + g]      = r4[0];
                rowpart[w * 32 + 8 + g]  = r4[1];
                rowpart[w * 32 + 16 + g] = r4[2];
                rowpart[w * 32 + 24 + g] = r4[3];
            }
            __syncthreads();
            if (tid < 32) {
                float s = 0.0f;
#pragma unroll
                for (int ww = 0; ww < 16; ww++) s += rowpart[ww * 32 + tid];
                rinv[tid] = __fdividef(1.0f, s);
            }
            __syncthreads();

            u64 ri[2][2];
            {
                float a0 = rinv[g],      a1 = rinv[8 + g];
                float a2 = rinv[16 + g], a3 = rinv[24 + g];
                ri[0][0] = pk2(a0, a0); ri[0][1] = pk2(a1, a1);
                ri[1][0] = pk2(a2, a2); ri[1][1] = pk2(a3, a3);
            }

            float* pb = wr ? p_out + (size_t)bgh * kSEQ * kSEQ : nullptr;
            const int rowb = oct * 128 + qt * 32;
#pragma unroll
            for (int i = 0; i < 2; i++) {
#pragma unroll
                for (int t = 0; t < 8; t++) {
                    u64 p01 = mul2(pk2(acc[i][t][0], acc[i][t][1]), ri[i][0]);
                    u64 p23 = mul2(pk2(acc[i][t][2], acc[i][t][3]), ri[i][1]);
                    cs2[t] = add2(cs2[t], add2(p01, p23));
                    if (wr) {
                        int col = w * 64 + t * 8 + t4 * 2;
                        float* a0 = pb + (size_t)(rowb + i * 16 + g) * kSEQ + col;
                        float* a1 = pb + (size_t)(rowb + i * 16 + 8 + g) * kSEQ + col;
                        asm volatile("st.global.cs.b64 [%0], %1;" :: "l"(a0), "l"(p01) : "memory");
                        asm volatile("st.global.cs.b64 [%0], %1;" :: "l"(a1), "l"(p23) : "memory");
                    }
                }
            }
        }

        // flush this item's column sums (128 q-rows worth)
#pragma unroll
        for (int t = 0; t < 8; t++) {
            float c0, c1;
            upk2(c0, c1, cs2[t]);
            c0 += __shfl_xor_sync(0xffffffffu, c0, 4);
            c1 += __shfl_xor_sync(0xffffffffu, c1, 4);
            c0 += __shfl_xor_sync(0xffffffffu, c0, 8);
            c1 += __shfl_xor_sync(0xffffffffu, c1, 8);
            c0 += __shfl_xor_sync(0xffffffffu, c0, 16);
            c1 += __shfl_xor_sync(0xffffffffu, c1, 16);
            if (g == 0) {
                int col = w * 64 + t * 8 + t4 * 2;
                atomicAdd(&g_pbar[(size_t)bgh * kSEQ + col], c0);
                atomicAdd(&g_pbar[(size_t)bgh * kSEQ + col + 1], c1);
            }
        }
    }
}

// ---------------- K3a: w[bg,h,d] = sum_s pbar[bg,h,s] * value[bg,s,d] ------------
__global__ __launch_bounds__(256) void wsum_kernel(const float* __restrict__ value)
{
    __shared__ float pbs[8 * 32];
    const int bg = blockIdx.x, sc = blockIdx.y;   // 32 chunks of 32 s
    const int tid = threadIdx.x;

    if (tid < 256) {
        int hh = tid >> 5, s = tid & 31;
        pbs[tid] = g_pbar[(size_t)bg * 8192 + hh * 1024 + sc * 32 + s];
    }
    __syncthreads();

    const int d0 = tid * 2;
    u64 a2[8];
#pragma unroll
    for (int hh = 0; hh < 8; hh++) a2[hh] = 0ULL;

    const u64* vb = (const u64*)(value + (size_t)bg * kSEQ * kD + (size_t)sc * 32 * kD + d0);
#pragma unroll 4
    for (int s = 0; s < 32; s++) {
        u64 v = vb[(size_t)s * 256];
#pragma unroll
        for (int hh = 0; hh < 8; hh++) {
            float pw = pbs[hh * 32 + s];
            a2[hh] = fma2(pk2(pw, pw), v, a2[hh]);
        }
    }
#pragma unroll
    for (int hh = 0; hh < 8; hh++) {
        float x, y;
        upk2(x, y, a2[hh]);
        atomicAdd(&g_w[(size_t)bg * 4096 + hh * 512 + d0],     x);
        atomicAdd(&g_w[(size_t)bg * 4096 + hh * 512 + d0 + 1], y);
    }
}

// ---------------- K3b: merged x-projection + y-projection ----------------------
__global__ __launch_bounds__(512) void final_kernel(
    const float* __restrict__ Wv, const float* __restrict__ bv,
    const float* __restrict__ Wo, const float* __restrict__ bo,
    float* __restrict__ y_out)
{
    __shared__ float ws[8 * 512];
    __shared__ float xs[512];
    const int bg = blockIdx.x, tid = threadIdx.x;
    for (int i = tid; i < 4096; i += 512) ws[i] = g_w[(size_t)bg * 4096 + i];
    __syncthreads();

    {
        const int hh = tid >> 6, dd = tid & 63;
        const float4* wv = (const float4*)(Wv + (size_t)(hh * 64 + dd) * 512);
        const float4* wrr = (const float4*)(ws + hh * 512);
        float a0 = 0.f, a1 = 0.f, a2 = 0.f, a3 = 0.f;
#pragma unroll 4
        for (int e = 0; e < 128; e++) {
            float4 x = wrr[e]; float4 y = wv[e];
            a0 = fmaf(x.x, y.x, a0); a1 = fmaf(x.y, y.y, a1);
            a2 = fmaf(x.z, y.z, a2); a3 = fmaf(x.w, y.w, a3);
        }
        xs[dd * 8 + hh] = bv[hh * 64 + dd] + ((a0 + a1) + (a2 + a3)) * (1.0f / 1024.0f);
    }
    __syncthreads();

    {
        const float4* wo = (const float4*)(Wo + (size_t)tid * 512);
        const float4* xr = (const float4*)xs;
        float a0 = 0.f, a1 = 0.f, a2 = 0.f, a3 = 0.f;
#pragma unroll 4
        for (int e = 0; e < 128; e++) {
            float4 x = xr[e]; float4 w = wo[e];
            a0 = fmaf(x.x, w.x, a0); a1 = fmaf(x.y, w.y, a1);
            a2 = fmaf(x.z, w.z, a2); a3 = fmaf(x.w, w.w, a3);
        }
        y_out[(size_t)bg * 512 + tid] = bo[tid] + ((a0 + a1) + (a2 + a3));
    }
}

// ---------------- launch ----------------
extern "C" void kernel_launch(void* const* d_in, const int* in_sizes, int n_in,
                              void* d_out, int out_size)
{
    const float* query = (const float*)d_in[0];
    const float* key   = (const float*)d_in[1];
    const float* value = (const float*)d_in[2];
    const float* Wq = (const float*)d_in[3];
    const float* bq = (const float*)d_in[4];
    const float* Wk = (const float*)d_in[5];
    const float* bk = (const float*)d_in[6];
    const float* Wv = (const float*)d_in[7];
    const float* bv = (const float*)d_in[8];
    const float* Wo = (const float*)d_in[9];
    const float* bo = (const float*)d_in[10];
    float* out = (float*)d_out;

    float* y_ptr = nullptr;
    float* p_ptr = nullptr;
    long long osz = (long long)out_size;
    if (osz == (long long)kYELEMS) {
        y_ptr = out;
    } else if (osz == kPELEMS) {
        p_ptr = out;
    } else {
        y_ptr = out;
        p_ptr = out + kYELEMS;
    }

    cudaFuncSetAttribute(attn_kernel, cudaFuncAttributeMaxDynamicSharedMemorySize, ATTN_SMEM);

    zero_kernel<<<(kZTOT + 255) / 256, 256>>>();                         // 1
    cvt_kernel<<<(kCVT_WK + 255) / 256, 256>>>(query, key, Wq, Wk);      // 2
    proj_kernel<<<dim3(kROWS / 128, kD / 128, 2), 256>>>(bq, bk);        // 3
    attn_kernel<<<kCTAS, 512, ATTN_SMEM>>>(p_ptr);                       // 4
    if (y_ptr) {
        wsum_kernel<<<dim3(kBG, 32), 256>>>(value);                      // 5
        final_kernel<<<kBG, 512>>>(Wv, bv, Wo, bo, y_ptr);               // 6
    }
}

// round 10
// speedup vs baseline: 1.0966x; 1.0966x over previous
#include <cuda_runtime.h>
#include <cuda_bf16.h>
#include <cstdint>

// ---------------- problem constants ----------------
#define kH     8
#define kD     512
#define kDK    64
#define kBG    24          // B*G = 4*6
#define kSEQ   1024
#define kROWS  (kBG * kSEQ)    // 24576
#define kBGH   (kBG * kH)      // 192
#define kYELEMS (kBG * kD)     // 12288
#define kSCALE (1.0f / 1200.0f)   // 1/(sqrt(64)*150)
#define kPELEMS 201326592LL
#define kITEMS (kBGH * 8)      // 1536 items = (bgh, 128-row octant)
#define kCTAS  148

typedef unsigned long long u64;
typedef unsigned int u32;

// ---------------- scratch ----------------
__device__ __align__(16) __nv_bfloat16 g_qx[kROWS * kD];   // bf16 query input
__device__ __align__(16) __nv_bfloat16 g_kx[kROWS * kD];   // bf16 key input
__device__ __align__(16) __nv_bfloat16 g_wq[kD * kD];      // bf16 Wq
__device__ __align__(16) __nv_bfloat16 g_wk[kD * kD];      // bf16 Wk
__device__ __align__(16) __nv_bfloat16 g_qb[kROWS * kD];   // bf16 Q projection
__device__ __align__(16) __nv_bfloat16 g_kb[kROWS * kD];   // bf16 K projection
__device__ float g_pbar[kBGH * kSEQ];
__device__ float g_w[kBG * kH * kD];

// ---------------- helpers ----------------
__device__ __forceinline__ u32 pack_bf2(float x, float y) {
    __nv_bfloat162 h = __floats2bfloat162_rn(x, y);
    return *reinterpret_cast<u32*>(&h);
}
__device__ __forceinline__ void mma_bf16(float c[4], const u32 a[4],
                                         u32 b0, u32 b1) {
    asm volatile(
        "mma.sync.aligned.m16n8k16.row.col.f32.bf16.bf16.f32 "
        "{%0,%1,%2,%3}, {%4,%5,%6,%7}, {%8,%9}, {%0,%1,%2,%3};\n"
        : "+f"(c[0]), "+f"(c[1]), "+f"(c[2]), "+f"(c[3])
        : "r"(a[0]), "r"(a[1]), "r"(a[2]), "r"(a[3]), "r"(b0), "r"(b1));
}
// packed f32x2
__device__ __forceinline__ u64 pk2(float x, float y) {
    u64 r; asm("mov.b64 %0, {%1,%2};" : "=l"(r) : "f"(x), "f"(y)); return r;
}
__device__ __forceinline__ void upk2(float& x, float& y, u64 v) {
    asm("mov.b64 {%0,%1}, %2;" : "=f"(x), "=f"(y) : "l"(v));
}
__device__ __forceinline__ u64 fma2(u64 a, u64 b, u64 c) {
    u64 d; asm("fma.rn.f32x2 %0,%1,%2,%3;" : "=l"(d) : "l"(a), "l"(b), "l"(c)); return d;
}
__device__ __forceinline__ u64 mul2(u64 a, u64 b) {
    u64 d; asm("mul.rn.f32x2 %0,%1,%2;" : "=l"(d) : "l"(a), "l"(b)); return d;
}
__device__ __forceinline__ u64 add2(u64 a, u64 b) {
    u64 d; asm("add.rn.f32x2 %0,%1,%2;" : "=l"(d) : "l"(a), "l"(b)); return d;
}
__device__ __forceinline__ void st128cs(float* p, u64 lo, u64 hi) {
    asm volatile("st.global.cs.v2.b64 [%0], {%1, %2};" :: "l"(p), "l"(lo), "l"(hi) : "memory");
}

// ---------------- K0: zero accumulators ----------------
#define kZTOT (kBGH * kSEQ + kBG * kH * kD)
__global__ void zero_kernel() {
    int i = blockIdx.x * blockDim.x + threadIdx.x;
    if (i < kBGH * kSEQ) g_pbar[i] = 0.0f;
    else if (i < kZTOT) g_w[i - kBGH * kSEQ] = 0.0f;
}

// ---------------- K0b/K0c: one-shot fp32 -> bf16 conversion (split in two) ------
#define kCVT_Q  3145728
#define kCVT_K  (kCVT_Q * 2)          // 6291456  (query+key, float4 groups)
#define kCVT_W  131072                // Wq+Wk, float4 groups
__global__ __launch_bounds__(256) void cvtqk_kernel(
    const float* __restrict__ query, const float* __restrict__ key)
{
    long long i = (long long)blockIdx.x * blockDim.x + threadIdx.x;
    if (i >= kCVT_K) return;
    const float* src;  __nv_bfloat16* dst;  long long off;
    if (i < kCVT_Q) { src = query; dst = g_qx; off = i; }
    else            { src = key;   dst = g_kx; off = i - kCVT_Q; }
    float4 v = *(const float4*)(src + off * 4);
    *(uint2*)(dst + off * 4) = make_uint2(pack_bf2(v.x, v.y), pack_bf2(v.z, v.w));
}
__global__ __launch_bounds__(256) void cvtw_kernel(
    const float* __restrict__ Wq, const float* __restrict__ Wk)
{
    long long i = (long long)blockIdx.x * blockDim.x + threadIdx.x;
    if (i >= kCVT_W) return;
    const float* src;  __nv_bfloat16* dst;  long long off;
    if (i < kCVT_W / 2) { src = Wq; dst = g_wq; off = i; }
    else                { src = Wk; dst = g_wk; off = i - kCVT_W / 2; }
    float4 v = *(const float4*)(src + off * 4);
    *(uint2*)(dst + off * 4) = make_uint2(pack_bf2(v.x, v.y), pack_bf2(v.z, v.w));
}

// ---------------- K1: Q & K projections (bf16 inputs) ----------
__global__ __launch_bounds__(256, 2) void proj_kernel(
    const float* __restrict__ bq, const float* __restrict__ bk)
{
    __shared__ __nv_bfloat16 As[128 * 72];
    __shared__ __nv_bfloat16 Bs[128 * 72];

    const int z = blockIdx.z;
    const __nv_bfloat16* X = z ? g_kx : g_qx;
    const __nv_bfloat16* W = z ? g_wk : g_wq;
    const float* bias = z ? bk : bq;
    __nv_bfloat16* out = z ? g_kb : g_qb;

    const int mbase = blockIdx.x * 128;
    const int nbase = blockIdx.y * 128;
    const int tid = threadIdx.x;
    const int lane = tid & 31, wid = tid >> 5;
    const int wm = wid >> 1, wn = wid & 1;
    const int g = lane >> 2, t4 = lane & 3;

    float acc[2][8][4];
#pragma unroll
    for (int i = 0; i < 2; i++)
#pragma unroll
        for (int t = 0; t < 8; t++)
#pragma unroll
            for (int c = 0; c < 4; c++) acc[i][t][c] = 0.0f;

    for (int kc = 0; kc < 512; kc += 64) {
#pragma unroll
        for (int it = 0; it < 4; it++) {
            int idx = tid + it * 256;
            int r = idx >> 3, c16 = idx & 7;
            *(uint4*)(As + r * 72 + c16 * 8) =
                *(const uint4*)(X + (size_t)(mbase + r) * 512 + kc + c16 * 8);
            *(uint4*)(Bs + r * 72 + c16 * 8) =
                *(const uint4*)(W + (size_t)(nbase + r) * 512 + kc + c16 * 8);
        }
        __syncthreads();

#pragma unroll
        for (int kk = 0; kk < 4; kk++) {
            u32 a[2][4];
#pragma unroll
            for (int i = 0; i < 2; i++) {
                int rb = wm * 32 + i * 16;
                a[i][0] = *(const u32*)(As + (rb + g) * 72 + kk * 16 + t4 * 2);
                a[i][1] = *(const u32*)(As + (rb + 8 + g) * 72 + kk * 16 + t4 * 2);
                a[i][2] = *(const u32*)(As + (rb + g) * 72 + kk * 16 + 8 + t4 * 2);
                a[i][3] = *(const u32*)(As + (rb + 8 + g) * 72 + kk * 16 + 8 + t4 * 2);
            }
#pragma unroll
            for (int t = 0; t < 8; t++) {
                int srow = wn * 64 + t * 8 + g;
                u32 b0 = *(const u32*)(Bs + srow * 72 + kk * 16 + t4 * 2);
                u32 b1 = *(const u32*)(Bs + srow * 72 + kk * 16 + 8 + t4 * 2);
                mma_bf16(acc[0][t], a[0], b0, b1);
                mma_bf16(acc[1][t], a[1], b0, b1);
            }
        }
        __syncthreads();
    }

#pragma unroll
    for (int i = 0; i < 2; i++) {
#pragma unroll
        for (int t = 0; t < 8; t++) {
            int row0 = mbase + wm * 32 + i * 16 + g;
            int col  = nbase + wn * 64 + t * 8 + t4 * 2;
            float b0v = bias[col], b1v = bias[col + 1];
            *(u32*)(out + (size_t)row0 * 512 + col) =
                pack_bf2(acc[i][t][0] + b0v, acc[i][t][1] + b1v);
            *(u32*)(out + (size_t)(row0 + 8) * 512 + col) =
                pack_bf2(acc[i][t][2] + b0v, acc[i][t][3] + b1v);
        }
    }
}

// ---------------- K2: persistent fused attention (R8 smem-K + v128 stores) ------
#define ATTN_SMEM (1024*72*2 + 2*32*72*2 + 16*32*4 + 32*4)

__global__ __launch_bounds__(512, 1) void attn_kernel(float* __restrict__ p_out)
{
    extern __shared__ char smem[];
    __nv_bfloat16* Ks = (__nv_bfloat16*)smem;                 // 1024 x 72
    __nv_bfloat16* Qs = Ks + 1024 * 72;                       // 2 x (32 x 72)
    float* rowpart = (float*)(Qs + 2 * 32 * 72);              // 16 x 32
    float* rinv = rowpart + 16 * 32;                          // 32

    const int cta = blockIdx.x;
    const int it0 = (cta * kITEMS) / kCTAS;
    const int it1 = ((cta + 1) * kITEMS) / kCTAS;
    const int tid = threadIdx.x;
    const int lane = tid & 31, w = tid >> 5;
    const int g = lane >> 2, t4 = lane & 3;

    const u64 SC2  = pk2(kSCALE, kSCALE);
    const u64 C24  = pk2(1.0f/24.0f, 1.0f/24.0f);
    const u64 C6   = pk2(1.0f/6.0f, 1.0f/6.0f);
    const u64 CH   = pk2(0.5f, 0.5f);
    const u64 ONE2 = pk2(1.0f, 1.0f);

    const bool wr = (p_out != nullptr);
    int cur_bgh = -1;

    for (int item = it0; item < it1; item++) {
        const int bgh = item >> 3, oct = item & 7;
        const int bg = bgh >> 3, h = bgh & 7;

        // load K strip once per bgh
        if (bgh != cur_bgh) {
            cur_bgh = bgh;
#pragma unroll 4
            for (int it = 0; it < 16; it++) {
                int idx = tid + it * 512;
                int s = idx >> 3, c8 = idx & 7;
                uint4 v = *(const uint4*)(g_kb + ((size_t)(bg * kSEQ + s)) * 512 + h * 64 + c8 * 8);
                uint2* dst = (uint2*)(Ks + s * 72 + c8 * 8);
                dst[0] = make_uint2(v.x, v.y); dst[1] = make_uint2(v.z, v.w);
            }
        }
        // load first Q tile (32 x 64) into buffer 0
        if (tid < 256) {
            int r = tid >> 3, c8 = tid & 7;
            uint4 v = *(const uint4*)(g_qb + ((size_t)(bg * kSEQ + oct * 128 + r)) * 512 + h * 64 + c8 * 8);
            uint2* dst = (uint2*)(Qs + r * 72 + c8 * 8);
            dst[0] = make_uint2(v.x, v.y); dst[1] = make_uint2(v.z, v.w);
        }
        __syncthreads();

        u64 cs2[8];
#pragma unroll
        for (int t = 0; t < 8; t++) cs2[t] = 0ULL;

        for (int qt = 0; qt < 4; qt++) {
            const __nv_bfloat16* Qc = Qs + (qt & 1) * (32 * 72);

            float acc[2][8][4];
#pragma unroll
            for (int i = 0; i < 2; i++)
#pragma unroll
                for (int t = 0; t < 8; t++)
#pragma unroll
                    for (int c = 0; c < 4; c++) acc[i][t][c] = 0.0f;

#pragma unroll
            for (int kk = 0; kk < 4; kk++) {
                u32 a[2][4];
#pragma unroll
                for (int i = 0; i < 2; i++) {
                    int rb = i * 16;
                    a[i][0] = *(const u32*)(Qc + (rb + g) * 72 + kk * 16 + t4 * 2);
                    a[i][1] = *(const u32*)(Qc + (rb + 8 + g) * 72 + kk * 16 + t4 * 2);
                    a[i][2] = *(const u32*)(Qc + (rb + g) * 72 + kk * 16 + 8 + t4 * 2);
                    a[i][3] = *(const u32*)(Qc + (rb + 8 + g) * 72 + kk * 16 + 8 + t4 * 2);
                }
#pragma unroll
                for (int t = 0; t < 8; t++) {
                    int srow = w * 64 + t * 8 + g;
                    u32 b0 = *(const u32*)(Ks + srow * 72 + kk * 16 + t4 * 2);
                    u32 b1 = *(const u32*)(Ks + srow * 72 + kk * 16 + 8 + t4 * 2);
                    mma_bf16(acc[0][t], a[0], b0, b1);
                    mma_bf16(acc[1][t], a[1], b0, b1);
                }
            }

            // prefetch next Q tile into the other buffer
            if (qt < 3 && tid < 256) {
                int r = tid >> 3, c8 = tid & 7;
                uint4 v = *(const uint4*)(g_qb +
                    ((size_t)(bg * kSEQ + oct * 128 + (qt + 1) * 32 + r)) * 512 + h * 64 + c8 * 8);
                uint2* dst = (uint2*)(Qs + ((qt & 1) ^ 1) * (32 * 72) + r * 72 + c8 * 8);
                dst[0] = make_uint2(v.x, v.y); dst[1] = make_uint2(v.z, v.w);
            }

            // exp (packed f32x2, degree-4 poly) written back into acc; row partials
            u64 rs2[2][2] = {0ULL, 0ULL, 0ULL, 0ULL};
#pragma unroll
            for (int i = 0; i < 2; i++) {
#pragma unroll
                for (int t = 0; t < 8; t++) {
                    u64 x01 = mul2(pk2(acc[i][t][0], acc[i][t][1]), SC2);
                    u64 p01 = fma2(x01, C24, C6);
                    p01 = fma2(p01, x01, CH);
                    p01 = fma2(p01, x01, ONE2);
                    p01 = fma2(p01, x01, ONE2);
                    upk2(acc[i][t][0], acc[i][t][1], p01);
                    rs2[i][0] = add2(rs2[i][0], p01);

                    u64 x23 = mul2(pk2(acc[i][t][2], acc[i][t][3]), SC2);
                    u64 p23 = fma2(x23, C24, C6);
                    p23 = fma2(p23, x23, CH);
                    p23 = fma2(p23, x23, ONE2);
                    p23 = fma2(p23, x23, ONE2);
                    upk2(acc[i][t][2], acc[i][t][3], p23);
                    rs2[i][1] = add2(rs2[i][1], p23);
                }
            }
            float r4[4];
#pragma unroll
            for (int i = 0; i < 2; i++) {
                float lo, hi;
                upk2(lo, hi, rs2[i][0]); r4[i * 2]     = lo + hi;
                upk2(lo, hi, rs2[i][1]); r4[i * 2 + 1] = lo + hi;
            }
#pragma unroll
            for (int j = 0; j < 4; j++) {
                r4[j] += __shfl_xor_sync(0xffffffffu, r4[j], 1);
                r4[j] += __shfl_xor_sync(0xffffffffu, r4[j], 2);
            }
            if (t4 == 0) {
                rowpart[w * 32 + g]      = r4[0];
                rowpart[w * 32 + 8 + g]  = r4[1];
                rowpart[w * 32 + 16 + g] = r4[2];
                rowpart[w * 32 + 24 + g] = r4[3];
            }
            __syncthreads();
            if (tid < 32) {
                float s = 0.0f;
#pragma unroll
                for (int ww = 0; ww < 16; ww++) s += rowpart[ww * 32 + tid];
                rinv[tid] = __fdividef(1.0f, s);
            }
            __syncthreads();

            u64 ri[2][2];
            {
                float a0 = rinv[g],      a1 = rinv[8 + g];
                float a2 = rinv[16 + g], a3 = rinv[24 + g];
                ri[0][0] = pk2(a0, a0); ri[0][1] = pk2(a1, a1);
                ri[1][0] = pk2(a2, a2); ri[1][1] = pk2(a3, a3);
            }

            float* pb = wr ? p_out + (size_t)bgh * kSEQ * kSEQ : nullptr;
            const int rowb = oct * 128 + qt * 32;
            const bool oddq = (t4 & 1);
#pragma unroll
            for (int i = 0; i < 2; i++) {
#pragma unroll
                for (int tp = 0; tp < 4; tp++) {
                    const int t0 = tp * 2, t1 = t0 + 1;
                    u64 a01 = mul2(pk2(acc[i][t0][0], acc[i][t0][1]), ri[i][0]);
                    u64 a23 = mul2(pk2(acc[i][t0][2], acc[i][t0][3]), ri[i][1]);
                    u64 b01 = mul2(pk2(acc[i][t1][0], acc[i][t1][1]), ri[i][0]);
                    u64 b23 = mul2(pk2(acc[i][t1][2], acc[i][t1][3]), ri[i][1]);
                    cs2[t0] = add2(cs2[t0], add2(a01, a23));
                    cs2[t1] = add2(cs2[t1], add2(b01, b23));
                    if (wr) {
                        // quad exchange: build 4 contiguous cols per lane.
                        // even t4 stores t0's cols [2*t4 .. 2*t4+3],
                        // odd  t4 stores t1's cols [2*t4-2 .. 2*t4+1].
                        u64 xa01 = __shfl_xor_sync(0xffffffffu, a01, 1);
                        u64 xb01 = __shfl_xor_sync(0xffffffffu, b01, 1);
                        u64 xa23 = __shfl_xor_sync(0xffffffffu, a23, 1);
                        u64 xb23 = __shfl_xor_sync(0xffffffffu, b23, 1);
                        u64 lo0 = oddq ? xb01 : a01;
                        u64 hi0 = oddq ? b01  : xa01;
                        u64 lo1 = oddq ? xb23 : a23;
                        u64 hi1 = oddq ? b23  : xa23;
                        int tsel = oddq ? t1 : t0;
                        int col = w * 64 + tsel * 8 + (t4 & 2) * 2;
                        float* addr0 = pb + (size_t)(rowb + i * 16 + g) * kSEQ + col;
                        st128cs(addr0, lo0, hi0);
                        st128cs(addr0 + 8 * kSEQ, lo1, hi1);
                    }
                }
            }
        }

        // flush this item's column sums (128 q-rows worth)
#pragma unroll
        for (int t = 0; t < 8; t++) {
            float c0, c1;
            upk2(c0, c1, cs2[t]);
            c0 += __shfl_xor_sync(0xffffffffu, c0, 4);
            c1 += __shfl_xor_sync(0xffffffffu, c1, 4);
            c0 += __shfl_xor_sync(0xffffffffu, c0, 8);
            c1 += __shfl_xor_sync(0xffffffffu, c1, 8);
            c0 += __shfl_xor_sync(0xffffffffu, c0, 16);
            c1 += __shfl_xor_sync(0xffffffffu, c1, 16);
            if (g == 0) {
                int col = w * 64 + t * 8 + t4 * 2;
                atomicAdd(&g_pbar[(size_t)bgh * kSEQ + col], c0);
                atomicAdd(&g_pbar[(size_t)bgh * kSEQ + col + 1], c1);
            }
        }
    }
}

// ---------------- K3a: w[bg,h,d] = sum_s pbar[bg,h,s] * value[bg,s,d] ------------
__global__ __launch_bounds__(256) void wsum_kernel(const float* __restrict__ value)
{
    __shared__ float pbs[8 * 32];
    const int bg = blockIdx.x, sc = blockIdx.y;   // 32 chunks of 32 s
    const int tid = threadIdx.x;

    if (tid < 256) {
        int hh = tid >> 5, s = tid & 31;
        pbs[tid] = g_pbar[(size_t)bg * 8192 + hh * 1024 + sc * 32 + s];
    }
    __syncthreads();

    const int d0 = tid * 2;
    u64 a2[8];
#pragma unroll
    for (int hh = 0; hh < 8; hh++) a2[hh] = 0ULL;

    const u64* vb = (const u64*)(value + (size_t)bg * kSEQ * kD + (size_t)sc * 32 * kD + d0);
#pragma unroll 4
    for (int s = 0; s < 32; s++) {
        u64 v = vb[(size_t)s * 256];
#pragma unroll
        for (int hh = 0; hh < 8; hh++) {
            float pw = pbs[hh * 32 + s];
            a2[hh] = fma2(pk2(pw, pw), v, a2[hh]);
        }
    }
#pragma unroll
    for (int hh = 0; hh < 8; hh++) {
        float x, y;
        upk2(x, y, a2[hh]);
        atomicAdd(&g_w[(size_t)bg * 4096 + hh * 512 + d0],     x);
        atomicAdd(&g_w[(size_t)bg * 4096 + hh * 512 + d0 + 1], y);
    }
}

// ---------------- K3b: merged x-projection + y-projection ----------------------
__global__ __launch_bounds__(512) void final_kernel(
    const float* __restrict__ Wv, const float* __restrict__ bv,
    const float* __restrict__ Wo, const float* __restrict__ bo,
    float* __restrict__ y_out)
{
    __shared__ float ws[8 * 512];
    __shared__ float xs[512];
    const int bg = blockIdx.x, tid = threadIdx.x;
    for (int i = tid; i < 4096; i += 512) ws[i] = g_w[(size_t)bg * 4096 + i];
    __syncthreads();

    {
        const int hh = tid >> 6, dd = tid & 63;
        const float4* wv = (const float4*)(Wv + (size_t)(hh * 64 + dd) * 512);
        const float4* wrr = (const float4*)(ws + hh * 512);
        float a0 = 0.f, a1 = 0.f, a2 = 0.f, a3 = 0.f;
#pragma unroll 4
        for (int e = 0; e < 128; e++) {
            float4 x = wrr[e]; float4 y = wv[e];
            a0 = fmaf(x.x, y.x, a0); a1 = fmaf(x.y, y.y, a1);
            a2 = fmaf(x.z, y.z, a2); a3 = fmaf(x.w, y.w, a3);
        }
        xs[dd * 8 + hh] = bv[hh * 64 + dd] + ((a0 + a1) + (a2 + a3)) * (1.0f / 1024.0f);
    }
    __syncthreads();

    {
        const float4* wo = (const float4*)(Wo + (size_t)tid * 512);
        const float4* xr = (const float4*)xs;
        float a0 = 0.f, a1 = 0.f, a2 = 0.f, a3 = 0.f;
#pragma unroll 4
        for (int e = 0; e < 128; e++) {
            float4 x = xr[e]; float4 w = wo[e];
            a0 = fmaf(x.x, w.x, a0); a1 = fmaf(x.y, w.y, a1);
            a2 = fmaf(x.z, w.z, a2); a3 = fmaf(x.w, w.w, a3);
        }
        y_out[(size_t)bg * 512 + tid] = bo[tid] + ((a0 + a1) + (a2 + a3));
    }
}

// ---------------- launch ----------------
extern "C" void kernel_launch(void* const* d_in, const int* in_sizes, int n_in,
                              void* d_out, int out_size)
{
    const float* query = (const float*)d_in[0];
    const float* key   = (const float*)d_in[1];
    const float* value = (const float*)d_in[2];
    const float* Wq = (const float*)d_in[3];
    const float* bq = (const float*)d_in[4];
    const float* Wk = (const float*)d_in[5];
    const float* bk = (const float*)d_in[6];
    const float* Wv = (const float*)d_in[7];
    const float* bv = (const float*)d_in[8];
    const float* Wo = (const float*)d_in[9];
    const float* bo = (const float*)d_in[10];
    float* out = (float*)d_out;

    float* y_ptr = nullptr;
    float* p_ptr = nullptr;
    long long osz = (long long)out_size;
    if (osz == (long long)kYELEMS) {
        y_ptr = out;
    } else if (osz == kPELEMS) {
        p_ptr = out;
    } else {
        y_ptr = out;
        p_ptr = out + kYELEMS;
    }

    cudaFuncSetAttribute(attn_kernel, cudaFuncAttributeMaxDynamicSharedMemorySize, ATTN_SMEM);

    zero_kernel<<<(kZTOT + 255) / 256, 256>>>();                         // 1
    cvtqk_kernel<<<(kCVT_K + 255) / 256, 256>>>(query, key);             // 2
    cvtw_kernel<<<(kCVT_W + 255) / 256, 256>>>(Wq, Wk);                  // 3
    proj_kernel<<<dim3(kROWS / 128, kD / 128, 2), 256>>>(bq, bk);        // 4 (ncu)
    attn_kernel<<<kCTAS, 512, ATTN_SMEM>>>(p_ptr);                       // 5
    if (y_ptr) {
        wsum_kernel<<<dim3(kBG, 32), 256>>>(value);                      // 6
        final_kernel<<<kBG, 512>>>(Wv, bv, Wo, bo, y_ptr);               // 7
    }
}

// round 11
// speedup vs baseline: 1.1487x; 1.0475x over previous
#include <cuda_runtime.h>
#include <cuda_bf16.h>
#include <cstdint>

// ---------------- problem constants ----------------
#define kH     8
#define kD     512
#define kDK    64
#define kBG    24          // B*G = 4*6
#define kSEQ   1024
#define kROWS  (kBG * kSEQ)    // 24576
#define kBGH   (kBG * kH)      // 192
#define kYELEMS (kBG * kD)     // 12288
#define kSCALE (1.0f / 1200.0f)   // 1/(sqrt(64)*150)
#define kPELEMS 201326592LL
#define kITEMS (kBGH * 8)      // 1536 items = (bgh, 128-row octant)
#define kCTAS  148

typedef unsigned long long u64;
typedef unsigned int u32;

// ---------------- scratch ----------------
__device__ __align__(16) __nv_bfloat16 g_qx[kROWS * kD];   // bf16 query input
__device__ __align__(16) __nv_bfloat16 g_kx[kROWS * kD];   // bf16 key input
__device__ __align__(16) __nv_bfloat16 g_wq[kD * kD];      // bf16 Wq
__device__ __align__(16) __nv_bfloat16 g_wk[kD * kD];      // bf16 Wk
__device__ __align__(16) __nv_bfloat16 g_qb[kROWS * kD];   // bf16 Q projection
__device__ __align__(16) __nv_bfloat16 g_kb[kROWS * kD];   // bf16 K projection
__device__ float g_pbar[kBGH * kSEQ];
__device__ float g_w[kBG * kH * kD];

// ---------------- helpers ----------------
__device__ __forceinline__ u32 pack_bf2(float x, float y) {
    __nv_bfloat162 h = __floats2bfloat162_rn(x, y);
    return *reinterpret_cast<u32*>(&h);
}
__device__ __forceinline__ u32 s2u(const void* p) {
    return (u32)__cvta_generic_to_shared(p);
}
__device__ __forceinline__ void ldsm4(u32& r0, u32& r1, u32& r2, u32& r3, u32 addr) {
    asm volatile("ldmatrix.sync.aligned.m8n8.x4.shared.b16 {%0,%1,%2,%3}, [%4];"
        : "=r"(r0), "=r"(r1), "=r"(r2), "=r"(r3) : "r"(addr));
}
__device__ __forceinline__ void mma_bf16(float c[4], const u32 a[4],
                                         u32 b0, u32 b1) {
    asm volatile(
        "mma.sync.aligned.m16n8k16.row.col.f32.bf16.bf16.f32 "
        "{%0,%1,%2,%3}, {%4,%5,%6,%7}, {%8,%9}, {%0,%1,%2,%3};\n"
        : "+f"(c[0]), "+f"(c[1]), "+f"(c[2]), "+f"(c[3])
        : "r"(a[0]), "r"(a[1]), "r"(a[2]), "r"(a[3]), "r"(b0), "r"(b1));
}
// packed f32x2
__device__ __forceinline__ u64 pk2(float x, float y) {
    u64 r; asm("mov.b64 %0, {%1,%2};" : "=l"(r) : "f"(x), "f"(y)); return r;
}
__device__ __forceinline__ void upk2(float& x, float& y, u64 v) {
    asm("mov.b64 {%0,%1}, %2;" : "=f"(x), "=f"(y) : "l"(v));
}
__device__ __forceinline__ u64 fma2(u64 a, u64 b, u64 c) {
    u64 d; asm("fma.rn.f32x2 %0,%1,%2,%3;" : "=l"(d) : "l"(a), "l"(b), "l"(c)); return d;
}
__device__ __forceinline__ u64 mul2(u64 a, u64 b) {
    u64 d; asm("mul.rn.f32x2 %0,%1,%2;" : "=l"(d) : "l"(a), "l"(b)); return d;
}
__device__ __forceinline__ u64 add2(u64 a, u64 b) {
    u64 d; asm("add.rn.f32x2 %0,%1,%2;" : "=l"(d) : "l"(a), "l"(b)); return d;
}
__device__ __forceinline__ void st128cs(float* p, u64 lo, u64 hi) {
    asm volatile("st.global.cs.v2.b64 [%0], {%1, %2};" :: "l"(p), "l"(lo), "l"(hi) : "memory");
}

// ---------------- K0: zero accumulators ----------------
#define kZTOT (kBGH * kSEQ + kBG * kH * kD)
__global__ void zero_kernel() {
    int i = blockIdx.x * blockDim.x + threadIdx.x;
    if (i < kBGH * kSEQ) g_pbar[i] = 0.0f;
    else if (i < kZTOT) g_w[i - kBGH * kSEQ] = 0.0f;
}

// ---------------- K0b/K0c: one-shot fp32 -> bf16 conversion (split in two) ------
#define kCVT_Q  3145728
#define kCVT_K  (kCVT_Q * 2)          // 6291456  (query+key, float4 groups)
#define kCVT_W  131072                // Wq+Wk, float4 groups
__global__ __launch_bounds__(256) void cvtqk_kernel(
    const float* __restrict__ query, const float* __restrict__ key)
{
    long long i = (long long)blockIdx.x * blockDim.x + threadIdx.x;
    if (i >= kCVT_K) return;
    const float* src;  __nv_bfloat16* dst;  long long off;
    if (i < kCVT_Q) { src = query; dst = g_qx; off = i; }
    else            { src = key;   dst = g_kx; off = i - kCVT_Q; }
    float4 v = *(const float4*)(src + off * 4);
    *(uint2*)(dst + off * 4) = make_uint2(pack_bf2(v.x, v.y), pack_bf2(v.z, v.w));
}
__global__ __launch_bounds__(256) void cvtw_kernel(
    const float* __restrict__ Wq, const float* __restrict__ Wk)
{
    long long i = (long long)blockIdx.x * blockDim.x + threadIdx.x;
    if (i >= kCVT_W) return;
    const float* src;  __nv_bfloat16* dst;  long long off;
    if (i < kCVT_W / 2) { src = Wq; dst = g_wq; off = i; }
    else                { src = Wk; dst = g_wk; off = i - kCVT_W / 2; }
    float4 v = *(const float4*)(src + off * 4);
    *(uint2*)(dst + off * 4) = make_uint2(pack_bf2(v.x, v.y), pack_bf2(v.z, v.w));
}

// ---------------- K1: Q & K projections (bf16 inputs, ldmatrix feeds) ----------
__global__ __launch_bounds__(256, 2) void proj_kernel(
    const float* __restrict__ bq, const float* __restrict__ bk)
{
    __shared__ __nv_bfloat16 As[128 * 72];
    __shared__ __nv_bfloat16 Bs[128 * 72];

    const int z = blockIdx.z;
    const __nv_bfloat16* X = z ? g_kx : g_qx;
    const __nv_bfloat16* W = z ? g_wk : g_wq;
    const float* bias = z ? bk : bq;
    __nv_bfloat16* out = z ? g_kb : g_qb;

    const int mbase = blockIdx.x * 128;
    const int nbase = blockIdx.y * 128;
    const int tid = threadIdx.x;
    const int lane = tid & 31, wid = tid >> 5;
    const int wm = wid >> 1, wn = wid & 1;
    const int g = lane >> 2, t4 = lane & 3;

    const u32 AsU = s2u(As), BsU = s2u(Bs);
    // ldmatrix lane-address components (constant per thread)
    const int a_row = (lane & 15), a_coff = (lane >> 4) << 3;
    const int b_row = ((lane >> 4) << 3) + (lane & 7);
    const int b_coff = ((lane >> 3) & 1) << 3;

    float acc[2][8][4];
#pragma unroll
    for (int i = 0; i < 2; i++)
#pragma unroll
        for (int t = 0; t < 8; t++)
#pragma unroll
            for (int c = 0; c < 4; c++) acc[i][t][c] = 0.0f;

    for (int kc = 0; kc < 512; kc += 64) {
#pragma unroll
        for (int it = 0; it < 4; it++) {
            int idx = tid + it * 256;
            int r = idx >> 3, c16 = idx & 7;
            *(uint4*)(As + r * 72 + c16 * 8) =
                *(const uint4*)(X + (size_t)(mbase + r) * 512 + kc + c16 * 8);
            *(uint4*)(Bs + r * 72 + c16 * 8) =
                *(const uint4*)(W + (size_t)(nbase + r) * 512 + kc + c16 * 8);
        }
        __syncthreads();

#pragma unroll
        for (int kk = 0; kk < 4; kk++) {
            u32 a[2][4];
#pragma unroll
            for (int i = 0; i < 2; i++) {
                u32 addr = AsU + (u32)(((wm * 32 + i * 16 + a_row) * 72 + kk * 16 + a_coff) * 2);
                ldsm4(a[i][0], a[i][1], a[i][2], a[i][3], addr);
            }
#pragma unroll
            for (int tp = 0; tp < 4; tp++) {
                u32 b[4];
                u32 addr = BsU + (u32)(((wn * 64 + tp * 16 + b_row) * 72 + kk * 16 + b_coff) * 2);
                ldsm4(b[0], b[1], b[2], b[3], addr);
                mma_bf16(acc[0][2 * tp],     a[0], b[0], b[1]);
                mma_bf16(acc[1][2 * tp],     a[1], b[0], b[1]);
                mma_bf16(acc[0][2 * tp + 1], a[0], b[2], b[3]);
                mma_bf16(acc[1][2 * tp + 1], a[1], b[2], b[3]);
            }
        }
        __syncthreads();
    }

#pragma unroll
    for (int i = 0; i < 2; i++) {
#pragma unroll
        for (int t = 0; t < 8; t++) {
            int row0 = mbase + wm * 32 + i * 16 + g;
            int col  = nbase + wn * 64 + t * 8 + t4 * 2;
            float b0v = bias[col], b1v = bias[col + 1];
            *(u32*)(out + (size_t)row0 * 512 + col) =
                pack_bf2(acc[i][t][0] + b0v, acc[i][t][1] + b1v);
            *(u32*)(out + (size_t)(row0 + 8) * 512 + col) =
                pack_bf2(acc[i][t][2] + b0v, acc[i][t][3] + b1v);
        }
    }
}

// ---------------- K2: persistent fused attention (ldmatrix + v128 stores) ------
#define ATTN_SMEM (1024*72*2 + 2*32*72*2 + 16*32*4 + 32*4)

__global__ __launch_bounds__(512, 1) void attn_kernel(float* __restrict__ p_out)
{
    extern __shared__ char smem[];
    __nv_bfloat16* Ks = (__nv_bfloat16*)smem;                 // 1024 x 72
    __nv_bfloat16* Qs = Ks + 1024 * 72;                       // 2 x (32 x 72)
    float* rowpart = (float*)(Qs + 2 * 32 * 72);              // 16 x 32
    float* rinv = rowpart + 16 * 32;                          // 32

    const int cta = blockIdx.x;
    const int it0 = (cta * kITEMS) / kCTAS;
    const int it1 = ((cta + 1) * kITEMS) / kCTAS;
    const int tid = threadIdx.x;
    const int lane = tid & 31, w = tid >> 5;
    const int g = lane >> 2, t4 = lane & 3;

    const u32 KsU = s2u(Ks), QsU0 = s2u(Qs);
    const int a_row = (lane & 15), a_coff = (lane >> 4) << 3;
    const int b_row = ((lane >> 4) << 3) + (lane & 7);
    const int b_coff = ((lane >> 3) & 1) << 3;

    const u64 SC2  = pk2(kSCALE, kSCALE);
    const u64 C24  = pk2(1.0f/24.0f, 1.0f/24.0f);
    const u64 C6   = pk2(1.0f/6.0f, 1.0f/6.0f);
    const u64 CH   = pk2(0.5f, 0.5f);
    const u64 ONE2 = pk2(1.0f, 1.0f);

    const bool wr = (p_out != nullptr);
    int cur_bgh = -1;

    for (int item = it0; item < it1; item++) {
        const int bgh = item >> 3, oct = item & 7;
        const int bg = bgh >> 3, h = bgh & 7;

        // load K strip once per bgh
        if (bgh != cur_bgh) {
            cur_bgh = bgh;
#pragma unroll 4
            for (int it = 0; it < 16; it++) {
                int idx = tid + it * 512;
                int s = idx >> 3, c8 = idx & 7;
                uint4 v = *(const uint4*)(g_kb + ((size_t)(bg * kSEQ + s)) * 512 + h * 64 + c8 * 8);
                uint2* dst = (uint2*)(Ks + s * 72 + c8 * 8);
                dst[0] = make_uint2(v.x, v.y); dst[1] = make_uint2(v.z, v.w);
            }
        }
        // load first Q tile (32 x 64) into buffer 0
        if (tid < 256) {
            int r = tid >> 3, c8 = tid & 7;
            uint4 v = *(const uint4*)(g_qb + ((size_t)(bg * kSEQ + oct * 128 + r)) * 512 + h * 64 + c8 * 8);
            uint2* dst = (uint2*)(Qs + r * 72 + c8 * 8);
            dst[0] = make_uint2(v.x, v.y); dst[1] = make_uint2(v.z, v.w);
        }
        __syncthreads();

        u64 cs2[8];
#pragma unroll
        for (int t = 0; t < 8; t++) cs2[t] = 0ULL;

        for (int qt = 0; qt < 4; qt++) {
            const u32 QcU = QsU0 + (u32)((qt & 1) * (32 * 72 * 2));

            float acc[2][8][4];
#pragma unroll
            for (int i = 0; i < 2; i++)
#pragma unroll
                for (int t = 0; t < 8; t++)
#pragma unroll
                    for (int c = 0; c < 4; c++) acc[i][t][c] = 0.0f;

#pragma unroll
            for (int kk = 0; kk < 4; kk++) {
                u32 a[2][4];
#pragma unroll
                for (int i = 0; i < 2; i++) {
                    u32 addr = QcU + (u32)(((i * 16 + a_row) * 72 + kk * 16 + a_coff) * 2);
                    ldsm4(a[i][0], a[i][1], a[i][2], a[i][3], addr);
                }
#pragma unroll
                for (int tp = 0; tp < 4; tp++) {
                    u32 b[4];
                    u32 addr = KsU + (u32)(((w * 64 + tp * 16 + b_row) * 72 + kk * 16 + b_coff) * 2);
                    ldsm4(b[0], b[1], b[2], b[3], addr);
                    mma_bf16(acc[0][2 * tp],     a[0], b[0], b[1]);
                    mma_bf16(acc[1][2 * tp],     a[1], b[0], b[1]);
                    mma_bf16(acc[0][2 * tp + 1], a[0], b[2], b[3]);
                    mma_bf16(acc[1][2 * tp + 1], a[1], b[2], b[3]);
                }
            }

            // prefetch next Q tile into the other buffer
            if (qt < 3 && tid < 256) {
                int r = tid >> 3, c8 = tid & 7;
                uint4 v = *(const uint4*)(g_qb +
                    ((size_t)(bg * kSEQ + oct * 128 + (qt + 1) * 32 + r)) * 512 + h * 64 + c8 * 8);
                uint2* dst = (uint2*)(Qs + ((qt & 1) ^ 1) * (32 * 72) + r * 72 + c8 * 8);
                dst[0] = make_uint2(v.x, v.y); dst[1] = make_uint2(v.z, v.w);
            }

            // exp (packed f32x2, degree-4 poly) written back into acc; row partials
            u64 rs2[2][2] = {0ULL, 0ULL, 0ULL, 0ULL};
#pragma unroll
            for (int i = 0; i < 2; i++) {
#pragma unroll
                for (int t = 0; t < 8; t++) {
                    u64 x01 = mul2(pk2(acc[i][t][0], acc[i][t][1]), SC2);
                    u64 p01 = fma2(x01, C24, C6);
                    p01 = fma2(p01, x01, CH);
                    p01 = fma2(p01, x01, ONE2);
                    p01 = fma2(p01, x01, ONE2);
                    upk2(acc[i][t][0], acc[i][t][1], p01);
                    rs2[i][0] = add2(rs2[i][0], p01);

                    u64 x23 = mul2(pk2(acc[i][t][2], acc[i][t][3]), SC2);
                    u64 p23 = fma2(x23, C24, C6);
                    p23 = fma2(p23, x23, CH);
                    p23 = fma2(p23, x23, ONE2);
                    p23 = fma2(p23, x23, ONE2);
                    upk2(acc[i][t][2], acc[i][t][3], p23);
                    rs2[i][1] = add2(rs2[i][1], p23);
                }
            }
            float r4[4];
#pragma unroll
            for (int i = 0; i < 2; i++) {
                float lo, hi;
                upk2(lo, hi, rs2[i][0]); r4[i * 2]     = lo + hi;
                upk2(lo, hi, rs2[i][1]); r4[i * 2 + 1] = lo + hi;
            }
#pragma unroll
            for (int j = 0; j < 4; j++) {
                r4[j] += __shfl_xor_sync(0xffffffffu, r4[j], 1);
                r4[j] += __shfl_xor_sync(0xffffffffu, r4[j], 2);
            }
            if (t4 == 0) {
                rowpart[w * 32 + g]      = r4[0];
                rowpart[w * 32 + 8 + g]  = r4[1];
                rowpart[w * 32 + 16 + g] = r4[2];
                rowpart[w * 32 + 24 + g] = r4[3];
            }
            __syncthreads();
            if (tid < 32) {
                float s = 0.0f;
#pragma unroll
                for (int ww = 0; ww < 16; ww++) s += rowpart[ww * 32 + tid];
                rinv[tid] = __fdividef(1.0f, s);
            }
            __syncthreads();

            u64 ri[2][2];
            {
                float a0 = rinv[g],      a1 = rinv[8 + g];
                float a2 = rinv[16 + g], a3 = rinv[24 + g];
                ri[0][0] = pk2(a0, a0); ri[0][1] = pk2(a1, a1);
                ri[1][0] = pk2(a2, a2); ri[1][1] = pk2(a3, a3);
            }

            float* pb = wr ? p_out + (size_t)bgh * kSEQ * kSEQ : nullptr;
            const int rowb = oct * 128 + qt * 32;
            const bool oddq = (t4 & 1);
#pragma unroll
            for (int i = 0; i < 2; i++) {
#pragma unroll
                for (int tp = 0; tp < 4; tp++) {
                    const int t0 = tp * 2, t1 = t0 + 1;
                    u64 a01 = mul2(pk2(acc[i][t0][0], acc[i][t0][1]), ri[i][0]);
                    u64 a23 = mul2(pk2(acc[i][t0][2], acc[i][t0][3]), ri[i][1]);
                    u64 b01 = mul2(pk2(acc[i][t1][0], acc[i][t1][1]), ri[i][0]);
                    u64 b23 = mul2(pk2(acc[i][t1][2], acc[i][t1][3]), ri[i][1]);
                    cs2[t0] = add2(cs2[t0], add2(a01, a23));
                    cs2[t1] = add2(cs2[t1], add2(b01, b23));
                    if (wr) {
                        u64 xa01 = __shfl_xor_sync(0xffffffffu, a01, 1);
                        u64 xb01 = __shfl_xor_sync(0xffffffffu, b01, 1);
                        u64 xa23 = __shfl_xor_sync(0xffffffffu, a23, 1);
                        u64 xb23 = __shfl_xor_sync(0xffffffffu, b23, 1);
                        u64 lo0 = oddq ? xb01 : a01;
                        u64 hi0 = oddq ? b01  : xa01;
                        u64 lo1 = oddq ? xb23 : a23;
                        u64 hi1 = oddq ? b23  : xa23;
                        int tsel = oddq ? t1 : t0;
                        int col = w * 64 + tsel * 8 + (t4 & 2) * 2;
                        float* addr0 = pb + (size_t)(rowb + i * 16 + g) * kSEQ + col;
                        st128cs(addr0, lo0, hi0);
                        st128cs(addr0 + 8 * kSEQ, lo1, hi1);
                    }
                }
            }
        }

        // flush this item's column sums (128 q-rows worth)
#pragma unroll
        for (int t = 0; t < 8; t++) {
            float c0, c1;
            upk2(c0, c1, cs2[t]);
            c0 += __shfl_xor_sync(0xffffffffu, c0, 4);
            c1 += __shfl_xor_sync(0xffffffffu, c1, 4);
            c0 += __shfl_xor_sync(0xffffffffu, c0, 8);
            c1 += __shfl_xor_sync(0xffffffffu, c1, 8);
            c0 += __shfl_xor_sync(0xffffffffu, c0, 16);
            c1 += __shfl_xor_sync(0xffffffffu, c1, 16);
            if (g == 0) {
                int col = w * 64 + t * 8 + t4 * 2;
                atomicAdd(&g_pbar[(size_t)bgh * kSEQ + col], c0);
                atomicAdd(&g_pbar[(size_t)bgh * kSEQ + col + 1], c1);
            }
        }
    }
}

// ---------------- K3a: w[bg,h,d] = sum_s pbar[bg,h,s] * value[bg,s,d] ------------
__global__ __launch_bounds__(256) void wsum_kernel(const float* __restrict__ value)
{
    __shared__ float pbs[8 * 32];
    const int bg = blockIdx.x, sc = blockIdx.y;   // 32 chunks of 32 s
    const int tid = threadIdx.x;

    if (tid < 256) {
        int hh = tid >> 5, s = tid & 31;
        pbs[tid] = g_pbar[(size_t)bg * 8192 + hh * 1024 + sc * 32 + s];
    }
    __syncthreads();

    const int d0 = tid * 2;
    u64 a2[8];
#pragma unroll
    for (int hh = 0; hh < 8; hh++) a2[hh] = 0ULL;

    const u64* vb = (const u64*)(value + (size_t)bg * kSEQ * kD + (size_t)sc * 32 * kD + d0);
#pragma unroll 4
    for (int s = 0; s < 32; s++) {
        u64 v = vb[(size_t)s * 256];
#pragma unroll
        for (int hh = 0; hh < 8; hh++) {
            float pw = pbs[hh * 32 + s];
            a2[hh] = fma2(pk2(pw, pw), v, a2[hh]);
        }
    }
#pragma unroll
    for (int hh = 0; hh < 8; hh++) {
        float x, y;
        upk2(x, y, a2[hh]);
        atomicAdd(&g_w[(size_t)bg * 4096 + hh * 512 + d0],     x);
        atomicAdd(&g_w[(size_t)bg * 4096 + hh * 512 + d0 + 1], y);
    }
}

// ---------------- K3b: merged x-projection + y-projection ----------------------
__global__ __launch_bounds__(512) void final_kernel(
    const float* __restrict__ Wv, const float* __restrict__ bv,
    const float* __restrict__ Wo, const float* __restrict__ bo,
    float* __restrict__ y_out)
{
    __shared__ float ws[8 * 512];
    __shared__ float xs[512];
    const int bg = blockIdx.x, tid = threadIdx.x;
    for (int i = tid; i < 4096; i += 512) ws[i] = g_w[(size_t)bg * 4096 + i];
    __syncthreads();

    {
        const int hh = tid >> 6, dd = tid & 63;
        const float4* wv = (const float4*)(Wv + (size_t)(hh * 64 + dd) * 512);
        const float4* wrr = (const float4*)(ws + hh * 512);
        float a0 = 0.f, a1 = 0.f, a2 = 0.f, a3 = 0.f;
#pragma unroll 4
        for (int e = 0; e < 128; e++) {
            float4 x = wrr[e]; float4 y = wv[e];
            a0 = fmaf(x.x, y.x, a0); a1 = fmaf(x.y, y.y, a1);
            a2 = fmaf(x.z, y.z, a2); a3 = fmaf(x.w, y.w, a3);
        }
        xs[dd * 8 + hh] = bv[hh * 64 + dd] + ((a0 + a1) + (a2 + a3)) * (1.0f / 1024.0f);
    }
    __syncthreads();

    {
        const float4* wo = (const float4*)(Wo + (size_t)tid * 512);
        const float4* xr = (const float4*)xs;
        float a0 = 0.f, a1 = 0.f, a2 = 0.f, a3 = 0.f;
#pragma unroll 4
        for (int e = 0; e < 128; e++) {
            float4 x = xr[e]; float4 w = wo[e];
            a0 = fmaf(x.x, w.x, a0); a1 = fmaf(x.y, w.y, a1);
            a2 = fmaf(x.z, w.z, a2); a3 = fmaf(x.w, w.w, a3);
        }
        y_out[(size_t)bg * 512 + tid] = bo[tid] + ((a0 + a1) + (a2 + a3));
    }
}

// ---------------- launch ----------------
extern "C" void kernel_launch(void* const* d_in, const int* in_sizes, int n_in,
                              void* d_out, int out_size)
{
    const float* query = (const float*)d_in[0];
    const float* key   = (const float*)d_in[1];
    const float* value = (const float*)d_in[2];
    const float* Wq = (const float*)d_in[3];
    const float* bq = (const float*)d_in[4];
    const float* Wk = (const float*)d_in[5];
    const float* bk = (const float*)d_in[6];
    const float* Wv = (const float*)d_in[7];
    const float* bv = (const float*)d_in[8];
    const float* Wo = (const float*)d_in[9];
    const float* bo = (const float*)d_in[10];
    float* out = (float*)d_out;

    float* y_ptr = nullptr;
    float* p_ptr = nullptr;
    long long osz = (long long)out_size;
    if (osz == (long long)kYELEMS) {
        y_ptr = out;
    } else if (osz == kPELEMS) {
        p_ptr = out;
    } else {
        y_ptr = out;
        p_ptr = out + kYELEMS;
    }

    cudaFuncSetAttribute(attn_kernel, cudaFuncAttributeMaxDynamicSharedMemorySize, ATTN_SMEM);

    zero_kernel<<<(kZTOT + 255) / 256, 256>>>();                         // 1
    cvtqk_kernel<<<(kCVT_K + 255) / 256, 256>>>(query, key);             // 2
    cvtw_kernel<<<(kCVT_W + 255) / 256, 256>>>(Wq, Wk);                  // 3
    proj_kernel<<<dim3(kROWS / 128, kD / 128, 2), 256>>>(bq, bk);        // 4 (ncu)
    attn_kernel<<<kCTAS, 512, ATTN_SMEM>>>(p_ptr);                       // 5
    if (y_ptr) {
        wsum_kernel<<<dim3(kBG, 32), 256>>>(value);                      // 6
        final_kernel<<<kBG, 512>>>(Wv, bv, Wo, bo, y_ptr);               // 7
    }
}